// round 3
// baseline (speedup 1.0000x reference)
#include <cuda_runtime.h>
#include <math.h>

#define BSZ   8
#define TLEN  4096
#define INF   256
#define HDIM  512
#define OUTF  256
#define MROWS (BSZ*TLEN)     /* 32768 */
#define CHUNK 64
#define NC    (TLEN/CHUNK)   /* 64 */

/* ---------------- scratch (device globals; no runtime allocation) -------- */
__device__ float g_A [(size_t)MROWS*HDIM];   /* sigmoid(f)            64 MB */
__device__ float g_Bv[(size_t)MROWS*HDIM];   /* sigmoid(i)*h_tilde    64 MB */
__device__ float g_h [(size_t)MROWS*HDIM];   /* hidden states         64 MB */
__device__ float g_sA[BSZ*NC*HDIM];
__device__ float g_sB[BSZ*NC*HDIM];
__device__ float g_sR[BSZ*NC*HDIM];
__device__ float g_bound[BSZ*NC*HDIM];

__device__ __forceinline__ float sigf(float x) {
    return 1.0f / (1.0f + __expf(-x));
}

/* =========================================================================
 * Kernel 1: gates GEMM + activation epilogue.
 * Computes, for every (m = b*T+t, h):
 *   gf = sum_k in[m,k]*W[k,h], gi = ..*W[k,h+512], gh = ..*W[k,h+1024]
 *   g_A = sigmoid(gf); g_Bv = sigmoid(gi)*gh
 * Block tile 128(m) x 64(h), KC=32, thread tile 8x4, 3 gate accumulators.
 * ========================================================================= */
__global__ __launch_bounds__(256, 1)
void gates_kernel(const float* __restrict__ inp, const float* __restrict__ Whg)
{
    __shared__ float sIn[32][129];        /* [k][m], padded             */
    __shared__ float sW[3][32][64];       /* [gate][k][n]               */

    const int m0 = blockIdx.x * 128;
    const int h0 = blockIdx.y * 64;
    const int tid = threadIdx.x;
    const int tx = tid & 15;              /* n dim: 16 * 4 = 64  */
    const int ty = tid >> 4;              /* m dim: 16 * 8 = 128 */

    float4 af[8], ai[8], ah[8];
    #pragma unroll
    for (int i = 0; i < 8; ++i) {
        af[i] = make_float4(0.f,0.f,0.f,0.f);
        ai[i] = make_float4(0.f,0.f,0.f,0.f);
        ah[i] = make_float4(0.f,0.f,0.f,0.f);
    }

    for (int k0 = 0; k0 < INF; k0 += 32) {
        /* load input tile 128x32, store transposed [k][m] */
        #pragma unroll
        for (int i = 0; i < 4; ++i) {
            int idx = tid + i * 256;          /* 0..1023 float4 */
            int k4 = idx & 7;                 /* 8 float4 per row */
            int r  = idx >> 3;                /* 0..127 */
            float4 v = *(const float4*)(inp + (size_t)(m0 + r) * INF + k0 + k4 * 4);
            int kk = k4 * 4;
            sIn[kk+0][r] = v.x; sIn[kk+1][r] = v.y;
            sIn[kk+2][r] = v.z; sIn[kk+3][r] = v.w;
        }
        /* load weight tiles: 3 gates x 32k x 64n = 1536 float4 */
        #pragma unroll
        for (int i = 0; i < 6; ++i) {
            int idx = tid + i * 256;          /* 0..1535 */
            int n4 = idx & 15;
            int k  = (idx >> 4) & 31;
            int g  = idx >> 9;                /* 0..2 */
            float4 v = *(const float4*)(Whg + (size_t)(k0 + k) * (3*HDIM) + g * HDIM + h0 + n4 * 4);
            *(float4*)&sW[g][k][n4 * 4] = v;
        }
        __syncthreads();

        #pragma unroll
        for (int k = 0; k < 32; ++k) {
            float a[8];
            #pragma unroll
            for (int i = 0; i < 8; ++i) a[i] = sIn[k][ty * 8 + i];
            float4 bf = *(const float4*)&sW[0][k][tx * 4];
            float4 bi = *(const float4*)&sW[1][k][tx * 4];
            float4 bh = *(const float4*)&sW[2][k][tx * 4];
            #pragma unroll
            for (int i = 0; i < 8; ++i) {
                af[i].x = fmaf(a[i], bf.x, af[i].x);
                af[i].y = fmaf(a[i], bf.y, af[i].y);
                af[i].z = fmaf(a[i], bf.z, af[i].z);
                af[i].w = fmaf(a[i], bf.w, af[i].w);
                ai[i].x = fmaf(a[i], bi.x, ai[i].x);
                ai[i].y = fmaf(a[i], bi.y, ai[i].y);
                ai[i].z = fmaf(a[i], bi.z, ai[i].z);
                ai[i].w = fmaf(a[i], bi.w, ai[i].w);
                ah[i].x = fmaf(a[i], bh.x, ah[i].x);
                ah[i].y = fmaf(a[i], bh.y, ah[i].y);
                ah[i].z = fmaf(a[i], bh.z, ah[i].z);
                ah[i].w = fmaf(a[i], bh.w, ah[i].w);
            }
        }
        __syncthreads();
    }

    /* epilogue: activations, fused */
    #pragma unroll
    for (int i = 0; i < 8; ++i) {
        size_t base = (size_t)(m0 + ty * 8 + i) * HDIM + h0 + tx * 4;
        float4 A4, B4;
        A4.x = sigf(af[i].x); A4.y = sigf(af[i].y);
        A4.z = sigf(af[i].z); A4.w = sigf(af[i].w);
        B4.x = sigf(ai[i].x) * ah[i].x;
        B4.y = sigf(ai[i].y) * ah[i].y;
        B4.z = sigf(ai[i].z) * ah[i].z;
        B4.w = sigf(ai[i].w) * ah[i].w;
        *(float4*)&g_A[base]  = A4;
        *(float4*)&g_Bv[base] = B4;
    }
}

/* =========================================================================
 * Kernel 2: per-chunk summary fold (A_c, B_c, reset_c).
 * lane = (b*NC + c)*H + h, 262144 lanes.
 * ========================================================================= */
__global__ void chunk_summary_kernel(const int* __restrict__ is_init)
{
    int lane = blockIdx.x * blockDim.x + threadIdx.x;
    int h  = lane & (HDIM - 1);
    int bc = lane >> 9;
    int c  = bc & (NC - 1);
    int b  = bc >> 6;
    int t0 = c * CHUNK;
    size_t idx = ((size_t)(b * TLEN + t0)) * HDIM + h;
    const int* ip = is_init + b * TLEN + t0;

    float A = 1.f, Bv = 0.f, r = 0.f;
    #pragma unroll 4
    for (int t = 0; t < CHUNK; ++t, idx += HDIM) {
        float a  = g_A[idx];
        float bv = g_Bv[idx];
        if (ip[t]) { A = a; Bv = bv; r = 1.f; }
        else       { Bv = fmaf(a, Bv, bv); A *= a; }
    }
    g_sA[lane] = A; g_sB[lane] = Bv; g_sR[lane] = r;
}

/* =========================================================================
 * Kernel 3: sequential scan over chunk summaries (tiny: 4096 lanes x 64).
 * Emits per-chunk entry hidden state g_bound.
 * ========================================================================= */
__global__ void chunk_scan_kernel(const float* __restrict__ h0p)
{
    int lane = blockIdx.x * blockDim.x + threadIdx.x;   /* < BSZ*H */
    int h = lane & (HDIM - 1);
    int b = lane >> 9;
    float h0v = h0p[b * HDIM + h];
    float hp = h0v;
    #pragma unroll 4
    for (int c = 0; c < NC; ++c) {
        int s = (b * NC + c) * HDIM + h;
        g_bound[s] = hp;
        float prev = (g_sR[s] > 0.f) ? h0v : hp;
        hp = fmaf(g_sA[s], prev, g_sB[s]);
    }
}

/* =========================================================================
 * Kernel 4: apply pass — recompute recurrence inside each chunk with the
 * known entry state, write hidden states; last chunk also writes h_n.
 * ========================================================================= */
__global__ void apply_scan_kernel(const int* __restrict__ is_init,
                                  const float* __restrict__ h0p,
                                  float* __restrict__ hn_out)
{
    int lane = blockIdx.x * blockDim.x + threadIdx.x;
    int h  = lane & (HDIM - 1);
    int bc = lane >> 9;
    int c  = bc & (NC - 1);
    int b  = bc >> 6;
    int t0 = c * CHUNK;

    float h0v = h0p[b * HDIM + h];
    float hv  = g_bound[lane];
    size_t idx = ((size_t)(b * TLEN + t0)) * HDIM + h;
    const int* ip = is_init + b * TLEN + t0;

    #pragma unroll 4
    for (int t = 0; t < CHUNK; ++t, idx += HDIM) {
        float a  = g_A[idx];
        float bv = g_Bv[idx];
        float prev = ip[t] ? h0v : hv;
        hv = fmaf(a, prev, bv);
        g_h[idx] = hv;
    }
    if (c == NC - 1) hn_out[b * HDIM + h] = hv;
}

/* =========================================================================
 * Kernel 5: output GEMM  out = h @ W_out   (32768 x 256, K=512).
 * Block tile 128x128, KC=32, thread tile 8x8.
 * ========================================================================= */
__global__ __launch_bounds__(256, 1)
void out_kernel(const float* __restrict__ Wout, float* __restrict__ out)
{
    __shared__ float sIn[32][129];     /* [k][m] transposed, padded */
    __shared__ float sW[32][132];      /* [k][n], padded            */

    const int m0 = blockIdx.x * 128;
    const int n0 = blockIdx.y * 128;
    const int tid = threadIdx.x;
    const int tx = tid & 15;           /* n: 16 * 8 = 128 */
    const int ty = tid >> 4;           /* m: 16 * 8 = 128 */

    float4 acc[8][2];
    #pragma unroll
    for (int i = 0; i < 8; ++i) {
        acc[i][0] = make_float4(0.f,0.f,0.f,0.f);
        acc[i][1] = make_float4(0.f,0.f,0.f,0.f);
    }

    for (int k0 = 0; k0 < HDIM; k0 += 32) {
        #pragma unroll
        for (int i = 0; i < 4; ++i) {
            int idx = tid + i * 256;
            int k4 = idx & 7;
            int r  = idx >> 3;
            float4 v = *(const float4*)&g_h[(size_t)(m0 + r) * HDIM + k0 + k4 * 4];
            int kk = k4 * 4;
            sIn[kk+0][r] = v.x; sIn[kk+1][r] = v.y;
            sIn[kk+2][r] = v.z; sIn[kk+3][r] = v.w;
        }
        #pragma unroll
        for (int i = 0; i < 4; ++i) {
            int idx = tid + i * 256;       /* 1024 float4 = 32k x 128n */
            int n4 = idx & 31;
            int k  = idx >> 5;
            float4 v = *(const float4*)(Wout + (size_t)(k0 + k) * OUTF + n0 + n4 * 4);
            *(float4*)&sW[k][n4 * 4] = v;
        }
        __syncthreads();

        #pragma unroll
        for (int k = 0; k < 32; ++k) {
            float a[8];
            #pragma unroll
            for (int i = 0; i < 8; ++i) a[i] = sIn[k][ty * 8 + i];
            float4 b0 = *(const float4*)&sW[k][tx * 8];
            float4 b1 = *(const float4*)&sW[k][tx * 8 + 4];
            #pragma unroll
            for (int i = 0; i < 8; ++i) {
                acc[i][0].x = fmaf(a[i], b0.x, acc[i][0].x);
                acc[i][0].y = fmaf(a[i], b0.y, acc[i][0].y);
                acc[i][0].z = fmaf(a[i], b0.z, acc[i][0].z);
                acc[i][0].w = fmaf(a[i], b0.w, acc[i][0].w);
                acc[i][1].x = fmaf(a[i], b1.x, acc[i][1].x);
                acc[i][1].y = fmaf(a[i], b1.y, acc[i][1].y);
                acc[i][1].z = fmaf(a[i], b1.z, acc[i][1].z);
                acc[i][1].w = fmaf(a[i], b1.w, acc[i][1].w);
            }
        }
        __syncthreads();
    }

    #pragma unroll
    for (int i = 0; i < 8; ++i) {
        size_t base = (size_t)(m0 + ty * 8 + i) * OUTF + n0 + tx * 8;
        *(float4*)&out[base]     = acc[i][0];
        *(float4*)&out[base + 4] = acc[i][1];
    }
}

/* ========================================================================= */
extern "C" void kernel_launch(void* const* d_in, const int* in_sizes, int n_in,
                              void* d_out, int out_size)
{
    const float* inp  = (const float*)d_in[0];   /* (8,4096,256)  */
    const int*   isin = (const int*)  d_in[1];   /* (8,4096,1)    */
    const float* h0   = (const float*)d_in[2];   /* (8,1,512)     */
    const float* Whg  = (const float*)d_in[3];   /* (256,1536)    */
    const float* Wout = (const float*)d_in[4];   /* (512,256)     */
    float* out = (float*)d_out;                  /* out then h_n  */

    dim3 g1(MROWS / 128, HDIM / 64);
    gates_kernel<<<g1, 256>>>(inp, Whg);

    chunk_summary_kernel<<<(BSZ * NC * HDIM) / 256, 256>>>(isin);
    chunk_scan_kernel<<<(BSZ * HDIM) / 256, 256>>>(h0);
    apply_scan_kernel<<<(BSZ * NC * HDIM) / 256, 256>>>(isin, h0,
                                                        out + (size_t)MROWS * OUTF);

    dim3 g2(MROWS / 128, OUTF / 128);
    out_kernel<<<g2, 256>>>(Wout, out);
}

// round 6
// speedup vs baseline: 1.8032x; 1.8032x over previous
#include <cuda_runtime.h>
#include <cuda_bf16.h>
#include <cstdint>
#include <math.h>

#define BSZ   8
#define TLEN  4096
#define INF   256
#define HDIM  512
#define OUTF  256
#define MROWS (BSZ*TLEN)     /* 32768 */
#define CHUNK 64
#define NC    (TLEN/CHUNK)   /* 64 */

/* ---------------- scratch (device globals; no runtime allocation) -------- */
__device__ __align__(16) float g_A [(size_t)MROWS*HDIM];
__device__ __align__(16) float g_Bv[(size_t)MROWS*HDIM];
__device__ __align__(16) unsigned short g_in_hi[(size_t)MROWS*INF];
__device__ __align__(16) unsigned short g_in_lo[(size_t)MROWS*INF];
__device__ __align__(16) unsigned short g_WhgT_hi[3*HDIM*INF];  /* [1536][256] */
__device__ __align__(16) unsigned short g_WhgT_lo[3*HDIM*INF];
__device__ __align__(16) unsigned short g_WoutT_hi[OUTF*HDIM];  /* [256][512]  */
__device__ __align__(16) unsigned short g_WoutT_lo[OUTF*HDIM];
__device__ __align__(16) unsigned short g_h_hi[(size_t)MROWS*HDIM];
__device__ __align__(16) unsigned short g_h_lo[(size_t)MROWS*HDIM];
__device__ __align__(16) float g_sA[BSZ*NC*HDIM];
__device__ __align__(16) float g_sB[BSZ*NC*HDIM];
__device__ __align__(16) float g_sR[BSZ*NC*HDIM];
__device__ __align__(16) float g_bound[BSZ*NC*HDIM];

__device__ __forceinline__ float sigf(float x) {
    return 1.0f / (1.0f + __expf(-x));
}

__device__ __forceinline__ uint32_t smem_u32(const void* p) {
    uint32_t a;
    asm("{ .reg .u64 t; cvta.to.shared.u64 t, %1; cvt.u32.u64 %0, t; }"
        : "=r"(a) : "l"(p));
    return a;
}

#define CP_ASYNC16(dst, src) \
    asm volatile("cp.async.cg.shared.global [%0], [%1], 16;" :: "r"(dst), "l"(src))
#define CP_COMMIT()  asm volatile("cp.async.commit_group;" ::: "memory")
#define CP_WAIT(N)   asm volatile("cp.async.wait_group %0;" :: "n"(N) : "memory")

__device__ __forceinline__ void ldsm4(uint32_t r[4], uint32_t addr) {
    asm volatile("ldmatrix.sync.aligned.m8n8.x4.shared.b16 {%0,%1,%2,%3}, [%4];"
        : "=r"(r[0]), "=r"(r[1]), "=r"(r[2]), "=r"(r[3]) : "r"(addr));
}

__device__ __forceinline__ void mma_bf16(float c[4], const uint32_t a[4],
                                         uint32_t b0, uint32_t b1) {
    asm volatile(
        "mma.sync.aligned.m16n8k16.row.col.f32.bf16.bf16.f32 "
        "{%0,%1,%2,%3}, {%4,%5,%6,%7}, {%8,%9}, {%0,%1,%2,%3};"
        : "+f"(c[0]), "+f"(c[1]), "+f"(c[2]), "+f"(c[3])
        : "r"(a[0]), "r"(a[1]), "r"(a[2]), "r"(a[3]), "r"(b0), "r"(b1));
}

/* ====================== conversion / split kernels ======================= */
__global__ void conv_input_kernel(const float* __restrict__ x)
{
    int i = blockIdx.x * blockDim.x + threadIdx.x;       /* per float4 */
    float4 v = ((const float4*)x)[i];
    __nv_bfloat16 h0 = __float2bfloat16(v.x), h1 = __float2bfloat16(v.y);
    __nv_bfloat16 h2 = __float2bfloat16(v.z), h3 = __float2bfloat16(v.w);
    ushort4 hv, lv;
    hv.x = __bfloat16_as_ushort(h0); hv.y = __bfloat16_as_ushort(h1);
    hv.z = __bfloat16_as_ushort(h2); hv.w = __bfloat16_as_ushort(h3);
    lv.x = __bfloat16_as_ushort(__float2bfloat16(v.x - __bfloat162float(h0)));
    lv.y = __bfloat16_as_ushort(__float2bfloat16(v.y - __bfloat162float(h1)));
    lv.z = __bfloat16_as_ushort(__float2bfloat16(v.z - __bfloat162float(h2)));
    lv.w = __bfloat16_as_ushort(__float2bfloat16(v.w - __bfloat162float(h3)));
    ((ushort4*)g_in_hi)[i] = hv;
    ((ushort4*)g_in_lo)[i] = lv;
}

__global__ void conv_whg_kernel(const float* __restrict__ W)
{
    int i = blockIdx.x * blockDim.x + threadIdx.x;  /* i = n*256 + k */
    int n = i >> 8, k = i & 255;
    float v = W[(size_t)k * (3 * HDIM) + n];
    __nv_bfloat16 h = __float2bfloat16(v);
    g_WhgT_hi[i] = __bfloat16_as_ushort(h);
    g_WhgT_lo[i] = __bfloat16_as_ushort(__float2bfloat16(v - __bfloat162float(h)));
}

__global__ void conv_wout_kernel(const float* __restrict__ W)
{
    int i = blockIdx.x * blockDim.x + threadIdx.x;  /* i = n*512 + k */
    int n = i >> 9, k = i & 511;
    float v = W[(size_t)k * OUTF + n];
    __nv_bfloat16 h = __float2bfloat16(v);
    g_WoutT_hi[i] = __bfloat16_as_ushort(h);
    g_WoutT_lo[i] = __bfloat16_as_ushort(__float2bfloat16(v - __bfloat162float(h)));
}

/* =========================================================================
 * Gates GEMM via mma.sync bf16 3-pass split.
 * CTA: 128 m x (3 gates x 64 h). Warps 2m x 4n -> warp tile 64m x 48n.
 * K=256 in 8 chunks of 32, cp.async double-buffered.
 * Fused sigmoid epilogue via SMEM staging.
 * ========================================================================= */
#define G1_AHI  0
#define G1_ALO  10240
#define G1_BHI  20480
#define G1_BLO  35840
#define G1_STG  51200
#define G1_SMEM 102400
#define SPITCH  196

__global__ __launch_bounds__(256, 1) void gates_mma_kernel()
{
    extern __shared__ char smem[];
    uint32_t sb = smem_u32(smem);
    const int tid = threadIdx.x, lane = tid & 31, wid = tid >> 5;
    const int m0 = blockIdx.x * 128, h0 = blockIdx.y * 64;
    const int wm = wid >> 2, wn = wid & 3;

    float acc[4][6][4];
    #pragma unroll
    for (int a = 0; a < 4; ++a)
        #pragma unroll
        for (int b = 0; b < 6; ++b)
            acc[a][b][0] = acc[a][b][1] = acc[a][b][2] = acc[a][b][3] = 0.f;

    const char* aH = (const char*)g_in_hi;
    const char* aL = (const char*)g_in_lo;
    const char* bH = (const char*)g_WhgT_hi;
    const char* bL = (const char*)g_WhgT_lo;

    /* ---- chunk loader: 2560 x 16B segments, 10 per thread ---- */
    #define G1_LOAD(c) do {                                                   \
        uint32_t stg = sb + ((c) & 1) * G1_STG;                               \
        int k0 = (c) * 32;                                                    \
        _Pragma("unroll")                                                     \
        for (int it = 0; it < 10; ++it) {                                     \
            int idx = tid + it * 256;                                         \
            if (idx < 1024) {                                                 \
                int sp = idx >> 9, rem = idx & 511, r = rem >> 2, sg = rem & 3; \
                const char* src = (sp ? aL : aH)                              \
                    + ((size_t)(m0 + r) * INF + k0) * 2 + sg * 16;            \
                CP_ASYNC16(stg + (sp ? G1_ALO : G1_AHI) + r * 80 + sg * 16, src); \
            } else {                                                          \
                int j = idx - 1024;                                           \
                int sp = (j >= 768) ? 1 : 0, rem = j - sp * 768;              \
                int r = rem >> 2, sg = rem & 3;                               \
                const char* src = (sp ? bL : bH)                              \
                    + ((size_t)((r >> 6) * HDIM + h0 + (r & 63)) * INF + k0) * 2 \
                    + sg * 16;                                                \
                CP_ASYNC16(stg + (sp ? G1_BLO : G1_BHI) + r * 80 + sg * 16, src); \
            }                                                                 \
        }                                                                     \
        CP_COMMIT();                                                          \
    } while (0)

    G1_LOAD(0);
    #pragma unroll 1
    for (int c = 0; c < 8; ++c) {
        if (c + 1 < 8) { G1_LOAD(c + 1); CP_WAIT(1); }
        else           { CP_WAIT(0); }
        __syncthreads();
        uint32_t stg = sb + (c & 1) * G1_STG;

        #pragma unroll
        for (int ks = 0; ks < 2; ++ks) {
            const int kb = ks * 32;                 /* 16 elems = 32 bytes */
            uint32_t ah[4][4], al[4][4], bh[3][4], bl[3][4];
            #pragma unroll
            for (int mi = 0; mi < 4; ++mi) {
                uint32_t ad = stg + G1_AHI
                    + (wm * 64 + mi * 16 + (lane & 15)) * 80
                    + (lane >> 4) * 16 + kb;
                ldsm4(ah[mi], ad);
                ldsm4(al[mi], ad + (G1_ALO - G1_AHI));
            }
            #pragma unroll
            for (int j = 0; j < 3; ++j) {
                int r = wn * 48 + j * 16 + ((lane >> 4) << 3) + (lane & 7);
                uint32_t bd = stg + G1_BHI + r * 80
                    + ((lane >> 3) & 1) * 16 + kb;
                ldsm4(bh[j], bd);
                ldsm4(bl[j], bd + (G1_BLO - G1_BHI));
            }
            #pragma unroll
            for (int mi = 0; mi < 4; ++mi)
                #pragma unroll
                for (int nb = 0; nb < 6; ++nb) {
                    uint32_t b0h = bh[nb >> 1][(nb & 1) * 2];
                    uint32_t b1h = bh[nb >> 1][(nb & 1) * 2 + 1];
                    uint32_t b0l = bl[nb >> 1][(nb & 1) * 2];
                    uint32_t b1l = bl[nb >> 1][(nb & 1) * 2 + 1];
                    mma_bf16(acc[mi][nb], ah[mi], b0h, b1h);
                    mma_bf16(acc[mi][nb], ah[mi], b0l, b1l);
                    mma_bf16(acc[mi][nb], al[mi], b0h, b1h);
                }
        }
        __syncthreads();
    }

    /* ---- epilogue: stage accums, fuse sigmoid ---- */
    float* spad = (float*)smem;
    #pragma unroll
    for (int mi = 0; mi < 4; ++mi)
        #pragma unroll
        for (int nb = 0; nb < 6; ++nb) {
            int row = wm * 64 + mi * 16 + (lane >> 2);
            int col = wn * 48 + nb * 8 + (lane & 3) * 2;
            spad[row * SPITCH + col]           = acc[mi][nb][0];
            spad[row * SPITCH + col + 1]       = acc[mi][nb][1];
            spad[(row + 8) * SPITCH + col]     = acc[mi][nb][2];
            spad[(row + 8) * SPITCH + col + 1] = acc[mi][nb][3];
        }
    __syncthreads();

    const int h4 = (tid & 15) * 4, mr = tid >> 4;
    #pragma unroll
    for (int i = 0; i < 8; ++i) {
        int m = mr + i * 16;
        float4 gf = *(float4*)&spad[m * SPITCH + h4];
        float4 gi = *(float4*)&spad[m * SPITCH + 64 + h4];
        float4 gh = *(float4*)&spad[m * SPITCH + 128 + h4];
        float4 A4, B4;
        A4.x = sigf(gf.x); A4.y = sigf(gf.y);
        A4.z = sigf(gf.z); A4.w = sigf(gf.w);
        B4.x = sigf(gi.x) * gh.x; B4.y = sigf(gi.y) * gh.y;
        B4.z = sigf(gi.z) * gh.z; B4.w = sigf(gi.w) * gh.w;
        size_t base = (size_t)(m0 + m) * HDIM + h0 + h4;
        *(float4*)&g_A [base] = A4;
        *(float4*)&g_Bv[base] = B4;
    }
}

/* =========================================================================
 * Output GEMM: out = h @ W_out.  CTA 128m x 128n, K=512 in 16 chunks of 32.
 * Warps 2m x 4n -> warp tile 64m x 32n.
 * ========================================================================= */
#define G2_AHI  0
#define G2_ALO  10240
#define G2_BHI  20480
#define G2_BLO  30720
#define G2_STG  40960
#define G2_SMEM 81920

__global__ __launch_bounds__(256, 1) void out_mma_kernel(float* __restrict__ out)
{
    extern __shared__ char smem[];
    uint32_t sb = smem_u32(smem);
    const int tid = threadIdx.x, lane = tid & 31, wid = tid >> 5;
    const int m0 = blockIdx.x * 128, n0 = blockIdx.y * 128;
    const int wm = wid >> 2, wn = wid & 3;

    float acc[4][4][4];
    #pragma unroll
    for (int a = 0; a < 4; ++a)
        #pragma unroll
        for (int b = 0; b < 4; ++b)
            acc[a][b][0] = acc[a][b][1] = acc[a][b][2] = acc[a][b][3] = 0.f;

    const char* aH = (const char*)g_h_hi;
    const char* aL = (const char*)g_h_lo;
    const char* bH = (const char*)g_WoutT_hi;
    const char* bL = (const char*)g_WoutT_lo;

    #define G2_LOAD(c) do {                                                   \
        uint32_t stg = sb + ((c) & 1) * G2_STG;                               \
        int k0 = (c) * 32;                                                    \
        _Pragma("unroll")                                                     \
        for (int it = 0; it < 8; ++it) {                                      \
            int idx = tid + it * 256;                                         \
            int isB = idx >> 10;                                              \
            int j = idx & 1023;                                               \
            int sp = j >> 9, rem = j & 511, r = rem >> 2, sg = rem & 3;       \
            const char* src;                                                  \
            uint32_t dst;                                                     \
            if (isB) {                                                        \
                src = (sp ? bL : bH)                                          \
                    + ((size_t)(n0 + r) * HDIM + k0) * 2 + sg * 16;           \
                dst = stg + (sp ? G2_BLO : G2_BHI) + r * 80 + sg * 16;        \
            } else {                                                          \
                src = (sp ? aL : aH)                                          \
                    + ((size_t)(m0 + r) * HDIM + k0) * 2 + sg * 16;           \
                dst = stg + (sp ? G2_ALO : G2_AHI) + r * 80 + sg * 16;        \
            }                                                                 \
            CP_ASYNC16(dst, src);                                             \
        }                                                                     \
        CP_COMMIT();                                                          \
    } while (0)

    G2_LOAD(0);
    #pragma unroll 1
    for (int c = 0; c < 16; ++c) {
        if (c + 1 < 16) { G2_LOAD(c + 1); CP_WAIT(1); }
        else            { CP_WAIT(0); }
        __syncthreads();
        uint32_t stg = sb + (c & 1) * G2_STG;

        #pragma unroll
        for (int ks = 0; ks < 2; ++ks) {
            const int kb = ks * 32;
            uint32_t ah[4][4], al[4][4], bh[2][4], bl[2][4];
            #pragma unroll
            for (int mi = 0; mi < 4; ++mi) {
                uint32_t ad = stg + G2_AHI
                    + (wm * 64 + mi * 16 + (lane & 15)) * 80
                    + (lane >> 4) * 16 + kb;
                ldsm4(ah[mi], ad);
                ldsm4(al[mi], ad + (G2_ALO - G2_AHI));
            }
            #pragma unroll
            for (int j = 0; j < 2; ++j) {
                int r = wn * 32 + j * 16 + ((lane >> 4) << 3) + (lane & 7);
                uint32_t bd = stg + G2_BHI + r * 80
                    + ((lane >> 3) & 1) * 16 + kb;
                ldsm4(bh[j], bd);
                ldsm4(bl[j], bd + (G2_BLO - G2_BHI));
            }
            #pragma unroll
            for (int mi = 0; mi < 4; ++mi)
                #pragma unroll
                for (int nb = 0; nb < 4; ++nb) {
                    uint32_t b0h = bh[nb >> 1][(nb & 1) * 2];
                    uint32_t b1h = bh[nb >> 1][(nb & 1) * 2 + 1];
                    uint32_t b0l = bl[nb >> 1][(nb & 1) * 2];
                    uint32_t b1l = bl[nb >> 1][(nb & 1) * 2 + 1];
                    mma_bf16(acc[mi][nb], ah[mi], b0h, b1h);
                    mma_bf16(acc[mi][nb], ah[mi], b0l, b1l);
                    mma_bf16(acc[mi][nb], al[mi], b0h, b1h);
                }
        }
        __syncthreads();
    }

    /* direct epilogue */
    #pragma unroll
    for (int mi = 0; mi < 4; ++mi)
        #pragma unroll
        for (int nb = 0; nb < 4; ++nb) {
            int row = m0 + wm * 64 + mi * 16 + (lane >> 2);
            int col = n0 + wn * 32 + nb * 8 + (lane & 3) * 2;
            *(float2*)&out[(size_t)row * OUTF + col] =
                make_float2(acc[mi][nb][0], acc[mi][nb][1]);
            *(float2*)&out[(size_t)(row + 8) * OUTF + col] =
                make_float2(acc[mi][nb][2], acc[mi][nb][3]);
        }
}

/* ======================== scan kernels ================================== */
__global__ void chunk_summary_kernel(const int* __restrict__ is_init)
{
    int lane = blockIdx.x * blockDim.x + threadIdx.x;
    int h  = lane & (HDIM - 1);
    int bc = lane >> 9;
    int c  = bc & (NC - 1);
    int b  = bc >> 6;
    int t0 = c * CHUNK;
    size_t idx = ((size_t)(b * TLEN + t0)) * HDIM + h;
    const int* ip = is_init + b * TLEN + t0;

    float A = 1.f, Bv = 0.f, r = 0.f;
    #pragma unroll 4
    for (int t = 0; t < CHUNK; ++t, idx += HDIM) {
        float a  = g_A[idx];
        float bv = g_Bv[idx];
        if (ip[t]) { A = a; Bv = bv; r = 1.f; }
        else       { Bv = fmaf(a, Bv, bv); A *= a; }
    }
    g_sA[lane] = A; g_sB[lane] = Bv; g_sR[lane] = r;
}

__global__ void chunk_scan_kernel(const float* __restrict__ h0p)
{
    int lane = blockIdx.x * blockDim.x + threadIdx.x;   /* < BSZ*H */
    int h = lane & (HDIM - 1);
    int b = lane >> 9;
    float h0v = h0p[b * HDIM + h];
    float hp = h0v;
    #pragma unroll 4
    for (int c = 0; c < NC; ++c) {
        int s = (b * NC + c) * HDIM + h;
        g_bound[s] = hp;
        float prev = (g_sR[s] > 0.f) ? h0v : hp;
        hp = fmaf(g_sA[s], prev, g_sB[s]);
    }
}

__global__ void apply_scan_kernel(const int* __restrict__ is_init,
                                  const float* __restrict__ h0p,
                                  float* __restrict__ hn_out)
{
    int lane = blockIdx.x * blockDim.x + threadIdx.x;
    int h  = lane & (HDIM - 1);
    int bc = lane >> 9;
    int c  = bc & (NC - 1);
    int b  = bc >> 6;
    int t0 = c * CHUNK;

    float h0v = h0p[b * HDIM + h];
    float hv  = g_bound[lane];
    size_t idx = ((size_t)(b * TLEN + t0)) * HDIM + h;
    const int* ip = is_init + b * TLEN + t0;

    #pragma unroll 4
    for (int t = 0; t < CHUNK; ++t, idx += HDIM) {
        float a  = g_A[idx];
        float bv = g_Bv[idx];
        float prev = ip[t] ? h0v : hv;
        hv = fmaf(a, prev, bv);
        __nv_bfloat16 hh = __float2bfloat16(hv);
        g_h_hi[idx] = __bfloat16_as_ushort(hh);
        g_h_lo[idx] = __bfloat16_as_ushort(
            __float2bfloat16(hv - __bfloat162float(hh)));
    }
    if (c == NC - 1) hn_out[b * HDIM + h] = hv;
}

/* ========================================================================= */
extern "C" void kernel_launch(void* const* d_in, const int* in_sizes, int n_in,
                              void* d_out, int out_size)
{
    const float* inp  = (const float*)d_in[0];   /* (8,4096,256)  */
    const int*   isin = (const int*)  d_in[1];   /* (8,4096,1)    */
    const float* h0   = (const float*)d_in[2];   /* (8,1,512)     */
    const float* Whg  = (const float*)d_in[3];   /* (256,1536)    */
    const float* Wout = (const float*)d_in[4];   /* (512,256)     */
    float* out = (float*)d_out;                  /* out then h_n  */

    cudaFuncSetAttribute(gates_mma_kernel,
                         cudaFuncAttributeMaxDynamicSharedMemorySize, G1_SMEM);
    cudaFuncSetAttribute(out_mma_kernel,
                         cudaFuncAttributeMaxDynamicSharedMemorySize, G2_SMEM);

    conv_input_kernel<<<(MROWS * INF / 4) / 256, 256>>>(inp);
    conv_whg_kernel<<<(3 * HDIM * INF) / 256, 256>>>(Whg);
    conv_wout_kernel<<<(OUTF * HDIM) / 256, 256>>>(Wout);

    gates_mma_kernel<<<dim3(MROWS / 128, HDIM / 64), 256, G1_SMEM>>>();

    chunk_summary_kernel<<<(BSZ * NC * HDIM) / 256, 256>>>(isin);
    chunk_scan_kernel<<<(BSZ * HDIM) / 256, 256>>>(h0);
    apply_scan_kernel<<<(BSZ * NC * HDIM) / 256, 256>>>(isin, h0,
                                                        out + (size_t)MROWS * OUTF);

    out_mma_kernel<<<dim3(MROWS / 128, OUTF / 128), 256, G2_SMEM>>>(out);
}

// round 8
// speedup vs baseline: 1.8759x; 1.0403x over previous
#include <cuda_runtime.h>
#include <cuda_bf16.h>
#include <cstdint>
#include <math.h>

#define BSZ   8
#define TLEN  4096
#define INF   256
#define HDIM  512
#define OUTF  256
#define MROWS (BSZ*TLEN)     /* 32768 */
#define CHUNK 64
#define NC    (TLEN/CHUNK)   /* 64 */

/* ---------------- scratch (device globals; no runtime allocation) -------- */
__device__ __align__(16) float g_A [(size_t)MROWS*HDIM];
__device__ __align__(16) float g_Bv[(size_t)MROWS*HDIM];
__device__ __align__(16) unsigned short g_in_hi[(size_t)MROWS*INF];
__device__ __align__(16) unsigned short g_in_lo[(size_t)MROWS*INF];
__device__ __align__(16) unsigned short g_WhgT_hi[3*HDIM*INF];  /* [1536][256] */
__device__ __align__(16) unsigned short g_WhgT_lo[3*HDIM*INF];
__device__ __align__(16) unsigned short g_WoutT_hi[OUTF*HDIM];  /* [256][512]  */
__device__ __align__(16) unsigned short g_WoutT_lo[OUTF*HDIM];
__device__ __align__(16) unsigned short g_h_hi[(size_t)MROWS*HDIM];
__device__ __align__(16) unsigned short g_h_lo[(size_t)MROWS*HDIM];
__device__ __align__(16) float g_sA[BSZ*NC*HDIM];
__device__ __align__(16) float g_sB[BSZ*NC*HDIM];
__device__ __align__(16) float g_sR[BSZ*NC*HDIM];
__device__ __align__(16) float g_bound[BSZ*NC*HDIM];

__device__ __forceinline__ float sigf(float x) {
    return 1.0f / (1.0f + __expf(-x));
}

__device__ __forceinline__ uint32_t smem_u32(const void* p) {
    uint32_t a;
    asm("{ .reg .u64 t; cvta.to.shared.u64 t, %1; cvt.u32.u64 %0, t; }"
        : "=r"(a) : "l"(p));
    return a;
}

#define CP_ASYNC16(dst, src) \
    asm volatile("cp.async.cg.shared.global [%0], [%1], 16;" :: "r"(dst), "l"(src))
#define CP_COMMIT()  asm volatile("cp.async.commit_group;" ::: "memory")
#define CP_WAIT(N)   asm volatile("cp.async.wait_group %0;" :: "n"(N) : "memory")

__device__ __forceinline__ void ldsm4(uint32_t r[4], uint32_t addr) {
    asm volatile("ldmatrix.sync.aligned.m8n8.x4.shared.b16 {%0,%1,%2,%3}, [%4];"
        : "=r"(r[0]), "=r"(r[1]), "=r"(r[2]), "=r"(r[3]) : "r"(addr));
}

__device__ __forceinline__ void mma_bf16(float c[4], const uint32_t a[4],
                                         uint32_t b0, uint32_t b1) {
    asm volatile(
        "mma.sync.aligned.m16n8k16.row.col.f32.bf16.bf16.f32 "
        "{%0,%1,%2,%3}, {%4,%5,%6,%7}, {%8,%9}, {%0,%1,%2,%3};"
        : "+f"(c[0]), "+f"(c[1]), "+f"(c[2]), "+f"(c[3])
        : "r"(a[0]), "r"(a[1]), "r"(a[2]), "r"(a[3]), "r"(b0), "r"(b1));
}

/* ====================== conversion / split kernels ======================= */
__global__ void conv_input_kernel(const float* __restrict__ x)
{
    int i = blockIdx.x * blockDim.x + threadIdx.x;       /* per float4 */
    float4 v = ((const float4*)x)[i];
    __nv_bfloat16 h0 = __float2bfloat16(v.x), h1 = __float2bfloat16(v.y);
    __nv_bfloat16 h2 = __float2bfloat16(v.z), h3 = __float2bfloat16(v.w);
    ushort4 hv, lv;
    hv.x = __bfloat16_as_ushort(h0); hv.y = __bfloat16_as_ushort(h1);
    hv.z = __bfloat16_as_ushort(h2); hv.w = __bfloat16_as_ushort(h3);
    lv.x = __bfloat16_as_ushort(__float2bfloat16(v.x - __bfloat162float(h0)));
    lv.y = __bfloat16_as_ushort(__float2bfloat16(v.y - __bfloat162float(h1)));
    lv.z = __bfloat16_as_ushort(__float2bfloat16(v.z - __bfloat162float(h2)));
    lv.w = __bfloat16_as_ushort(__float2bfloat16(v.w - __bfloat162float(h3)));
    ((ushort4*)g_in_hi)[i] = hv;
    ((ushort4*)g_in_lo)[i] = lv;
}

__global__ void conv_whg_kernel(const float* __restrict__ W)
{
    int i = blockIdx.x * blockDim.x + threadIdx.x;  /* i = n*256 + k */
    int n = i >> 8, k = i & 255;
    float v = W[(size_t)k * (3 * HDIM) + n];
    __nv_bfloat16 h = __float2bfloat16(v);
    g_WhgT_hi[i] = __bfloat16_as_ushort(h);
    g_WhgT_lo[i] = __bfloat16_as_ushort(__float2bfloat16(v - __bfloat162float(h)));
}

__global__ void conv_wout_kernel(const float* __restrict__ W)
{
    int i = blockIdx.x * blockDim.x + threadIdx.x;  /* i = n*512 + k */
    int n = i >> 9, k = i & 511;
    float v = W[(size_t)k * OUTF + n];
    __nv_bfloat16 h = __float2bfloat16(v);
    g_WoutT_hi[i] = __bfloat16_as_ushort(h);
    g_WoutT_lo[i] = __bfloat16_as_ushort(__float2bfloat16(v - __bfloat162float(h)));
}

/* =========================================================================
 * Gates GEMM via mma.sync bf16 3-pass split.
 * CTA: 512 thr, 128 m x (3 gates x 64 h). Warps 4m x 4n -> warp 32m x 48n.
 * K=256 in 8 chunks of 32, cp.async 4-stage pipeline.
 * Fused sigmoid epilogue via SMEM staging.
 * ========================================================================= */
#define G1_AHI  0
#define G1_ALO  10240
#define G1_BHI  20480
#define G1_BLO  35840
#define G1_STG  51200
#define G1_SMEM (4 * G1_STG)      /* 204800 */
#define SPITCH  196

__global__ __launch_bounds__(512, 1) void gates_mma_kernel()
{
    extern __shared__ char smem[];
    uint32_t sb = smem_u32(smem);
    const int tid = threadIdx.x, lane = tid & 31, wid = tid >> 5;
    const int m0 = blockIdx.x * 128, h0 = blockIdx.y * 64;
    const int wm = wid >> 2, wn = wid & 3;

    float acc[2][6][4];
    #pragma unroll
    for (int a = 0; a < 2; ++a)
        #pragma unroll
        for (int b = 0; b < 6; ++b)
            acc[a][b][0] = acc[a][b][1] = acc[a][b][2] = acc[a][b][3] = 0.f;

    const char* aH = (const char*)g_in_hi;
    const char* aL = (const char*)g_in_lo;
    const char* bH = (const char*)g_WhgT_hi;
    const char* bL = (const char*)g_WhgT_lo;

    /* ---- chunk loader: 2560 x 16B segments, 5 per thread (512 thr) ---- */
    #define G1_LOAD(c) do {                                                   \
        uint32_t stg = sb + ((c) & 3) * G1_STG;                               \
        int k0 = (c) * 32;                                                    \
        _Pragma("unroll")                                                     \
        for (int it = 0; it < 5; ++it) {                                      \
            int idx = tid + it * 512;                                         \
            if (idx < 1024) {                                                 \
                int sp = idx >> 9, rem = idx & 511, r = rem >> 2, sg = rem & 3; \
                const char* src = (sp ? aL : aH)                              \
                    + ((size_t)(m0 + r) * INF + k0) * 2 + sg * 16;            \
                CP_ASYNC16(stg + (sp ? G1_ALO : G1_AHI) + r * 80 + sg * 16, src); \
            } else {                                                          \
                int j = idx - 1024;                                           \
                int sp = (j >= 768) ? 1 : 0, rem = j - sp * 768;              \
                int r = rem >> 2, sg = rem & 3;                               \
                const char* src = (sp ? bL : bH)                              \
                    + ((size_t)((r >> 6) * HDIM + h0 + (r & 63)) * INF + k0) * 2 \
                    + sg * 16;                                                \
                CP_ASYNC16(stg + (sp ? G1_BLO : G1_BHI) + r * 80 + sg * 16, src); \
            }                                                                 \
        }                                                                     \
        CP_COMMIT();                                                          \
    } while (0)

    G1_LOAD(0); G1_LOAD(1); G1_LOAD(2);
    #pragma unroll 1
    for (int c = 0; c < 8; ++c) {
        if (c <= 5)      { CP_WAIT(2); }
        else if (c == 6) { CP_WAIT(1); }
        else             { CP_WAIT(0); }
        __syncthreads();
        if (c + 3 < 8) G1_LOAD(c + 3);
        uint32_t stg = sb + (c & 3) * G1_STG;

        #pragma unroll
        for (int ks = 0; ks < 2; ++ks) {
            const int kb = ks * 32;                 /* 16 elems = 32 bytes */
            uint32_t ah[2][4], al[2][4], bh[3][4], bl[3][4];
            #pragma unroll
            for (int mi = 0; mi < 2; ++mi) {
                uint32_t ad = stg + G1_AHI
                    + (wm * 32 + mi * 16 + (lane & 15)) * 80
                    + (lane >> 4) * 16 + kb;
                ldsm4(ah[mi], ad);
                ldsm4(al[mi], ad + (G1_ALO - G1_AHI));
            }
            #pragma unroll
            for (int j = 0; j < 3; ++j) {
                int r = wn * 48 + j * 16 + ((lane >> 4) << 3) + (lane & 7);
                uint32_t bd = stg + G1_BHI + r * 80
                    + ((lane >> 3) & 1) * 16 + kb;
                ldsm4(bh[j], bd);
                ldsm4(bl[j], bd + (G1_BLO - G1_BHI));
            }
            #pragma unroll
            for (int mi = 0; mi < 2; ++mi)
                #pragma unroll
                for (int nb = 0; nb < 6; ++nb) {
                    uint32_t b0h = bh[nb >> 1][(nb & 1) * 2];
                    uint32_t b1h = bh[nb >> 1][(nb & 1) * 2 + 1];
                    uint32_t b0l = bl[nb >> 1][(nb & 1) * 2];
                    uint32_t b1l = bl[nb >> 1][(nb & 1) * 2 + 1];
                    mma_bf16(acc[mi][nb], ah[mi], b0h, b1h);
                    mma_bf16(acc[mi][nb], ah[mi], b0l, b1l);
                    mma_bf16(acc[mi][nb], al[mi], b0h, b1h);
                }
        }
    }
    __syncthreads();

    /* ---- epilogue: stage accums, fuse sigmoid ---- */
    float* spad = (float*)smem;
    #pragma unroll
    for (int mi = 0; mi < 2; ++mi)
        #pragma unroll
        for (int nb = 0; nb < 6; ++nb) {
            int row = wm * 32 + mi * 16 + (lane >> 2);
            int col = wn * 48 + nb * 8 + (lane & 3) * 2;
            spad[row * SPITCH + col]           = acc[mi][nb][0];
            spad[row * SPITCH + col + 1]       = acc[mi][nb][1];
            spad[(row + 8) * SPITCH + col]     = acc[mi][nb][2];
            spad[(row + 8) * SPITCH + col + 1] = acc[mi][nb][3];
        }
    __syncthreads();

    const int h4 = (tid & 15) * 4, mr = tid >> 4;    /* mr: 0..31 */
    #pragma unroll
    for (int i = 0; i < 4; ++i) {
        int m = mr + i * 32;
        float4 gf = *(float4*)&spad[m * SPITCH + h4];
        float4 gi = *(float4*)&spad[m * SPITCH + 64 + h4];
        float4 gh = *(float4*)&spad[m * SPITCH + 128 + h4];
        float4 A4, B4;
        A4.x = sigf(gf.x); A4.y = sigf(gf.y);
        A4.z = sigf(gf.z); A4.w = sigf(gf.w);
        B4.x = sigf(gi.x) * gh.x; B4.y = sigf(gi.y) * gh.y;
        B4.z = sigf(gi.z) * gh.z; B4.w = sigf(gi.w) * gh.w;
        size_t base = (size_t)(m0 + m) * HDIM + h0 + h4;
        *(float4*)&g_A [base] = A4;
        *(float4*)&g_Bv[base] = B4;
    }
}

/* =========================================================================
 * Output GEMM: out = h @ W_out.  512 thr, CTA 128m x 128n, K=512, 16 chunks.
 * Warps 4m x 4n -> warp tile 32m x 32n. 4-stage pipeline.
 * ========================================================================= */
#define G2_AHI  0
#define G2_ALO  10240
#define G2_BHI  20480
#define G2_BLO  30720
#define G2_STG  40960
#define G2_SMEM (4 * G2_STG)     /* 163840 */

__global__ __launch_bounds__(512, 1) void out_mma_kernel(float* __restrict__ out)
{
    extern __shared__ char smem[];
    uint32_t sb = smem_u32(smem);
    const int tid = threadIdx.x, lane = tid & 31, wid = tid >> 5;
    const int m0 = blockIdx.x * 128, n0 = blockIdx.y * 128;
    const int wm = wid >> 2, wn = wid & 3;

    float acc[2][4][4];
    #pragma unroll
    for (int a = 0; a < 2; ++a)
        #pragma unroll
        for (int b = 0; b < 4; ++b)
            acc[a][b][0] = acc[a][b][1] = acc[a][b][2] = acc[a][b][3] = 0.f;

    const char* aH = (const char*)g_h_hi;
    const char* aL = (const char*)g_h_lo;
    const char* bH = (const char*)g_WoutT_hi;
    const char* bL = (const char*)g_WoutT_lo;

    /* 2048 segments, 4 per thread */
    #define G2_LOAD(c) do {                                                   \
        uint32_t stg = sb + ((c) & 3) * G2_STG;                               \
        int k0 = (c) * 32;                                                    \
        _Pragma("unroll")                                                     \
        for (int it = 0; it < 4; ++it) {                                      \
            int idx = tid + it * 512;                                         \
            int isB = idx >> 10;                                              \
            int j = idx & 1023;                                               \
            int sp = j >> 9, rem = j & 511, r = rem >> 2, sg = rem & 3;       \
            const char* src;                                                  \
            uint32_t dst;                                                     \
            if (isB) {                                                        \
                src = (sp ? bL : bH)                                          \
                    + ((size_t)(n0 + r) * HDIM + k0) * 2 + sg * 16;           \
                dst = stg + (sp ? G2_BLO : G2_BHI) + r * 80 + sg * 16;        \
            } else {                                                          \
                src = (sp ? aL : aH)                                          \
                    + ((size_t)(m0 + r) * HDIM + k0) * 2 + sg * 16;           \
                dst = stg + (sp ? G2_ALO : G2_AHI) + r * 80 + sg * 16;        \
            }                                                                 \
            CP_ASYNC16(dst, src);                                             \
        }                                                                     \
        CP_COMMIT();                                                          \
    } while (0)

    G2_LOAD(0); G2_LOAD(1); G2_LOAD(2);
    #pragma unroll 1
    for (int c = 0; c < 16; ++c) {
        if (c <= 13)      { CP_WAIT(2); }
        else if (c == 14) { CP_WAIT(1); }
        else              { CP_WAIT(0); }
        __syncthreads();
        if (c + 3 < 16) G2_LOAD(c + 3);
        uint32_t stg = sb + (c & 3) * G2_STG;

        #pragma unroll
        for (int ks = 0; ks < 2; ++ks) {
            const int kb = ks * 32;
            uint32_t ah[2][4], al[2][4], bh[2][4], bl[2][4];
            #pragma unroll
            for (int mi = 0; mi < 2; ++mi) {
                uint32_t ad = stg + G2_AHI
                    + (wm * 32 + mi * 16 + (lane & 15)) * 80
                    + (lane >> 4) * 16 + kb;
                ldsm4(ah[mi], ad);
                ldsm4(al[mi], ad + (G2_ALO - G2_AHI));
            }
            #pragma unroll
            for (int j = 0; j < 2; ++j) {
                int r = wn * 32 + j * 16 + ((lane >> 4) << 3) + (lane & 7);
                uint32_t bd = stg + G2_BHI + r * 80
                    + ((lane >> 3) & 1) * 16 + kb;
                ldsm4(bh[j], bd);
                ldsm4(bl[j], bd + (G2_BLO - G2_BHI));
            }
            #pragma unroll
            for (int mi = 0; mi < 2; ++mi)
                #pragma unroll
                for (int nb = 0; nb < 4; ++nb) {
                    uint32_t b0h = bh[nb >> 1][(nb & 1) * 2];
                    uint32_t b1h = bh[nb >> 1][(nb & 1) * 2 + 1];
                    uint32_t b0l = bl[nb >> 1][(nb & 1) * 2];
                    uint32_t b1l = bl[nb >> 1][(nb & 1) * 2 + 1];
                    mma_bf16(acc[mi][nb], ah[mi], b0h, b1h);
                    mma_bf16(acc[mi][nb], ah[mi], b0l, b1l);
                    mma_bf16(acc[mi][nb], al[mi], b0h, b1h);
                }
        }
    }

    /* direct epilogue */
    #pragma unroll
    for (int mi = 0; mi < 2; ++mi)
        #pragma unroll
        for (int nb = 0; nb < 4; ++nb) {
            int row = m0 + wm * 32 + mi * 16 + (lane >> 2);
            int col = n0 + wn * 32 + nb * 8 + (lane & 3) * 2;
            *(float2*)&out[(size_t)row * OUTF + col] =
                make_float2(acc[mi][nb][0], acc[mi][nb][1]);
            *(float2*)&out[(size_t)(row + 8) * OUTF + col] =
                make_float2(acc[mi][nb][2], acc[mi][nb][3]);
        }
}

/* ======================== scan kernels ================================== */
__global__ void chunk_summary_kernel(const int* __restrict__ is_init)
{
    int lane = blockIdx.x * blockDim.x + threadIdx.x;
    int h  = lane & (HDIM - 1);
    int bc = lane >> 9;
    int c  = bc & (NC - 1);
    int b  = bc >> 6;
    int t0 = c * CHUNK;
    size_t idx = ((size_t)(b * TLEN + t0)) * HDIM + h;
    const int* ip = is_init + b * TLEN + t0;

    float A = 1.f, Bv = 0.f, r = 0.f;
    #pragma unroll 4
    for (int t = 0; t < CHUNK; ++t, idx += HDIM) {
        float a  = g_A[idx];
        float bv = g_Bv[idx];
        if (ip[t]) { A = a; Bv = bv; r = 1.f; }
        else       { Bv = fmaf(a, Bv, bv); A *= a; }
    }
    g_sA[lane] = A; g_sB[lane] = Bv; g_sR[lane] = r;
}

__global__ void chunk_scan_kernel(const float* __restrict__ h0p)
{
    int lane = blockIdx.x * blockDim.x + threadIdx.x;   /* < BSZ*H */
    int h = lane & (HDIM - 1);
    int b = lane >> 9;
    float h0v = h0p[b * HDIM + h];
    float hp = h0v;
    #pragma unroll 4
    for (int c = 0; c < NC; ++c) {
        int s = (b * NC + c) * HDIM + h;
        g_bound[s] = hp;
        float prev = (g_sR[s] > 0.f) ? h0v : hp;
        hp = fmaf(g_sA[s], prev, g_sB[s]);
    }
}

__global__ void apply_scan_kernel(const int* __restrict__ is_init,
                                  const float* __restrict__ h0p,
                                  float* __restrict__ hn_out)
{
    int lane = blockIdx.x * blockDim.x + threadIdx.x;
    int h  = lane & (HDIM - 1);
    int bc = lane >> 9;
    int c  = bc & (NC - 1);
    int b  = bc >> 6;
    int t0 = c * CHUNK;

    float h0v = h0p[b * HDIM + h];
    float hv  = g_bound[lane];
    size_t idx = ((size_t)(b * TLEN + t0)) * HDIM + h;
    const int* ip = is_init + b * TLEN + t0;

    #pragma unroll 4
    for (int t = 0; t < CHUNK; ++t, idx += HDIM) {
        float a  = g_A[idx];
        float bv = g_Bv[idx];
        float prev = ip[t] ? h0v : hv;
        hv = fmaf(a, prev, bv);
        __nv_bfloat16 hh = __float2bfloat16(hv);
        g_h_hi[idx] = __bfloat16_as_ushort(hh);
        g_h_lo[idx] = __bfloat16_as_ushort(
            __float2bfloat16(hv - __bfloat162float(hh)));
    }
    if (c == NC - 1) hn_out[b * HDIM + h] = hv;
}

/* ========================================================================= */
extern "C" void kernel_launch(void* const* d_in, const int* in_sizes, int n_in,
                              void* d_out, int out_size)
{
    const float* inp  = (const float*)d_in[0];   /* (8,4096,256)  */
    const int*   isin = (const int*)  d_in[1];   /* (8,4096,1)    */
    const float* h0   = (const float*)d_in[2];   /* (8,1,512)     */
    const float* Whg  = (const float*)d_in[3];   /* (256,1536)    */
    const float* Wout = (const float*)d_in[4];   /* (512,256)     */
    float* out = (float*)d_out;                  /* out then h_n  */

    cudaFuncSetAttribute(gates_mma_kernel,
                         cudaFuncAttributeMaxDynamicSharedMemorySize, G1_SMEM);
    cudaFuncSetAttribute(out_mma_kernel,
                         cudaFuncAttributeMaxDynamicSharedMemorySize, G2_SMEM);

    conv_input_kernel<<<(MROWS * INF / 4) / 256, 256>>>(inp);
    conv_whg_kernel<<<(3 * HDIM * INF) / 256, 256>>>(Whg);
    conv_wout_kernel<<<(OUTF * HDIM) / 256, 256>>>(Wout);

    gates_mma_kernel<<<dim3(MROWS / 128, HDIM / 64), 512, G1_SMEM>>>();

    chunk_summary_kernel<<<(BSZ * NC * HDIM) / 256, 256>>>(isin);
    chunk_scan_kernel<<<(BSZ * HDIM) / 256, 256>>>(h0);
    apply_scan_kernel<<<(BSZ * NC * HDIM) / 256, 256>>>(isin, h0,
                                                        out + (size_t)MROWS * OUTF);

    out_mma_kernel<<<dim3(MROWS / 128, OUTF / 128), 512, G2_SMEM>>>(out);
}

// round 10
// speedup vs baseline: 2.2378x; 1.1929x over previous
#include <cuda_runtime.h>
#include <cuda_fp16.h>
#include <cstdint>
#include <math.h>

#define BSZ   8
#define TLEN  4096
#define INF   256
#define HDIM  512
#define OUTF  256
#define MROWS (BSZ*TLEN)     /* 32768 */
#define CHUNK 64
#define NC    (TLEN/CHUNK)   /* 64 */

/* ---------------- scratch (device globals; no runtime allocation) -------- */
__device__ __align__(16) float g_A [(size_t)MROWS*HDIM];
__device__ __align__(16) float g_Bv[(size_t)MROWS*HDIM];
__device__ __align__(16) unsigned short g_in_h[(size_t)MROWS*INF];     /* fp16 */
__device__ __align__(16) unsigned short g_Wg_hi[3*HDIM*INF];  /* [1536][256] */
__device__ __align__(16) unsigned short g_Wg_lo[3*HDIM*INF];
__device__ __align__(16) unsigned short g_wo_h[OUTF*HDIM];    /* [256][512]  */
__device__ __align__(16) unsigned short g_h_hi[(size_t)MROWS*HDIM];
__device__ __align__(16) unsigned short g_h_lo[(size_t)MROWS*HDIM];
__device__ __align__(16) float g_sA[BSZ*NC*HDIM];
__device__ __align__(16) float g_sB[BSZ*NC*HDIM];
__device__ __align__(16) float g_sR[BSZ*NC*HDIM];
__device__ __align__(16) float g_bound[BSZ*NC*HDIM];

__device__ __forceinline__ float sigf(float x) {
    return 1.0f / (1.0f + __expf(-x));
}

__device__ __forceinline__ uint32_t smem_u32(const void* p) {
    uint32_t a;
    asm("{ .reg .u64 t; cvta.to.shared.u64 t, %1; cvt.u32.u64 %0, t; }"
        : "=r"(a) : "l"(p));
    return a;
}

#define CP_ASYNC16(dst, src) \
    asm volatile("cp.async.cg.shared.global [%0], [%1], 16;" :: "r"(dst), "l"(src))
#define CP_COMMIT()  asm volatile("cp.async.commit_group;" ::: "memory")
#define CP_WAIT(N)   asm volatile("cp.async.wait_group %0;" :: "n"(N) : "memory")

__device__ __forceinline__ void ldsm4(uint32_t r[4], uint32_t addr) {
    asm volatile("ldmatrix.sync.aligned.m8n8.x4.shared.b16 {%0,%1,%2,%3}, [%4];"
        : "=r"(r[0]), "=r"(r[1]), "=r"(r[2]), "=r"(r[3]) : "r"(addr));
}

__device__ __forceinline__ void mma_f16(float c[4], const uint32_t a[4],
                                        uint32_t b0, uint32_t b1) {
    asm volatile(
        "mma.sync.aligned.m16n8k16.row.col.f32.f16.f16.f32 "
        "{%0,%1,%2,%3}, {%4,%5,%6,%7}, {%8,%9}, {%0,%1,%2,%3};"
        : "+f"(c[0]), "+f"(c[1]), "+f"(c[2]), "+f"(c[3])
        : "r"(a[0]), "r"(a[1]), "r"(a[2]), "r"(a[3]), "r"(b0), "r"(b1));
}

/* ====================== conversion / split kernels ======================= */
__global__ void conv_input_kernel(const float* __restrict__ x)
{
    int i = blockIdx.x * blockDim.x + threadIdx.x;       /* per float4 */
    float4 v = ((const float4*)x)[i];
    ushort4 hv;
    hv.x = __half_as_ushort(__float2half_rn(v.x));
    hv.y = __half_as_ushort(__float2half_rn(v.y));
    hv.z = __half_as_ushort(__float2half_rn(v.z));
    hv.w = __half_as_ushort(__float2half_rn(v.w));
    ((ushort4*)g_in_h)[i] = hv;
}

__global__ void conv_whg_kernel(const float* __restrict__ W)
{
    int i = blockIdx.x * blockDim.x + threadIdx.x;  /* i = n*256 + k */
    int n = i >> 8, k = i & 255;
    float v = W[(size_t)k * (3 * HDIM) + n];
    __half h = __float2half_rn(v);
    g_Wg_hi[i] = __half_as_ushort(h);
    g_Wg_lo[i] = __half_as_ushort(__float2half_rn(v - __half2float(h)));
}

__global__ void conv_wout_kernel(const float* __restrict__ W)
{
    int i = blockIdx.x * blockDim.x + threadIdx.x;  /* i = n*512 + k */
    int n = i >> 9, k = i & 511;
    g_wo_h[i] = __half_as_ushort(__float2half_rn(W[(size_t)k * OUTF + n]));
}

/* =========================================================================
 * Gates GEMM (fp16 2-pass: in_fp16 x (W_hi + W_lo)) + fused sigmoid
 * epilogue + fused per-chunk scan summary.
 * CTA: 512 thr, 128 m x (3 gates x 64 h). Warps 4m x 4n, warp 32m x 48n.
 * K=256 in 8 chunks of 32, cp.async 4-stage pipeline.
 * Epilogue scratch OVERLAPS the stage region (dead after mainloop):
 *   spad 0..100352, As 100352..135168, Bs 135168..169984, partials ..176128
 * ========================================================================= */
#define G1_A    0
#define G1_BHI  10240
#define G1_BLO  25600
#define G1_STG  40960
#define G1_AS   100352
#define G1_BS   135168
#define G1_PA   169984
#define G1_PB   172032
#define G1_PR   174080
#define G1_SMEM 176128      /* >= 4*G1_STG = 163840, fits 227KB cap */
#define SPITCH  196
#define APITCH  68

__global__ __launch_bounds__(512, 1)
void gates_mma_kernel(const int* __restrict__ is_init)
{
    extern __shared__ char smem[];
    uint32_t sb = smem_u32(smem);
    const int tid = threadIdx.x, lane = tid & 31, wid = tid >> 5;
    const int m0 = blockIdx.x * 128, h0 = blockIdx.y * 64;
    const int wm = wid >> 2, wn = wid & 3;

    float acc[2][6][4];
    #pragma unroll
    for (int a = 0; a < 2; ++a)
        #pragma unroll
        for (int b = 0; b < 6; ++b)
            acc[a][b][0] = acc[a][b][1] = acc[a][b][2] = acc[a][b][3] = 0.f;

    const char* aG = (const char*)g_in_h;
    const char* bH = (const char*)g_Wg_hi;
    const char* bL = (const char*)g_Wg_lo;

    /* ---- chunk loader: 2048 x 16B segments, 4 per thread ---- */
    #define G1_LOAD(c) do {                                                   \
        uint32_t stg = sb + ((c) & 3) * G1_STG;                               \
        int k0 = (c) * 32;                                                    \
        _Pragma("unroll")                                                     \
        for (int it = 0; it < 4; ++it) {                                      \
            int idx = tid + it * 512;                                         \
            if (idx < 512) {                                                  \
                int r = idx >> 2, sg = idx & 3;                               \
                const char* src = aG                                          \
                    + ((size_t)(m0 + r) * INF + k0) * 2 + sg * 16;            \
                CP_ASYNC16(stg + G1_A + r * 80 + sg * 16, src);               \
            } else {                                                          \
                int j = idx - 512;                                            \
                int sp = (j >= 768) ? 1 : 0, rem = j - sp * 768;              \
                int r = rem >> 2, sg = rem & 3;                               \
                const char* src = (sp ? bL : bH)                              \
                    + ((size_t)((r >> 6) * HDIM + h0 + (r & 63)) * INF + k0) * 2 \
                    + sg * 16;                                                \
                CP_ASYNC16(stg + (sp ? G1_BLO : G1_BHI) + r * 80 + sg * 16, src); \
            }                                                                 \
        }                                                                     \
        CP_COMMIT();                                                          \
    } while (0)

    G1_LOAD(0); G1_LOAD(1); G1_LOAD(2);
    #pragma unroll 1
    for (int c = 0; c < 8; ++c) {
        if (c <= 5)      { CP_WAIT(2); }
        else if (c == 6) { CP_WAIT(1); }
        else             { CP_WAIT(0); }
        __syncthreads();
        if (c + 3 < 8) G1_LOAD(c + 3);
        uint32_t stg = sb + (c & 3) * G1_STG;

        #pragma unroll
        for (int ks = 0; ks < 2; ++ks) {
            const int kb = ks * 32;                 /* 16 elems = 32 bytes */
            uint32_t ah[2][4], bh[3][4], bl[3][4];
            #pragma unroll
            for (int mi = 0; mi < 2; ++mi) {
                uint32_t ad = stg + G1_A
                    + (wm * 32 + mi * 16 + (lane & 15)) * 80
                    + (lane >> 4) * 16 + kb;
                ldsm4(ah[mi], ad);
            }
            #pragma unroll
            for (int j = 0; j < 3; ++j) {
                int r = wn * 48 + j * 16 + ((lane >> 4) << 3) + (lane & 7);
                uint32_t bd = stg + G1_BHI + r * 80
                    + ((lane >> 3) & 1) * 16 + kb;
                ldsm4(bh[j], bd);
                ldsm4(bl[j], bd + (G1_BLO - G1_BHI));
            }
            #pragma unroll
            for (int mi = 0; mi < 2; ++mi)
                #pragma unroll
                for (int nb = 0; nb < 6; ++nb) {
                    uint32_t b0h = bh[nb >> 1][(nb & 1) * 2];
                    uint32_t b1h = bh[nb >> 1][(nb & 1) * 2 + 1];
                    uint32_t b0l = bl[nb >> 1][(nb & 1) * 2];
                    uint32_t b1l = bl[nb >> 1][(nb & 1) * 2 + 1];
                    mma_f16(acc[mi][nb], ah[mi], b0h, b1h);
                    mma_f16(acc[mi][nb], ah[mi], b0l, b1l);
                }
        }
    }
    __syncthreads();

    /* ---- epilogue: stage accums, fuse sigmoid ---- */
    float* spad = (float*)smem;
    #pragma unroll
    for (int mi = 0; mi < 2; ++mi)
        #pragma unroll
        for (int nb = 0; nb < 6; ++nb) {
            int row = wm * 32 + mi * 16 + (lane >> 2);
            int col = wn * 48 + nb * 8 + (lane & 3) * 2;
            spad[row * SPITCH + col]           = acc[mi][nb][0];
            spad[row * SPITCH + col + 1]       = acc[mi][nb][1];
            spad[(row + 8) * SPITCH + col]     = acc[mi][nb][2];
            spad[(row + 8) * SPITCH + col + 1] = acc[mi][nb][3];
        }
    __syncthreads();

    float* As = (float*)(smem + G1_AS);
    float* Bs = (float*)(smem + G1_BS);
    const int h4 = (tid & 15) * 4, mr = tid >> 4;    /* mr: 0..31 */
    #pragma unroll
    for (int i = 0; i < 4; ++i) {
        int m = mr + i * 32;
        float4 gf = *(float4*)&spad[m * SPITCH + h4];
        float4 gi = *(float4*)&spad[m * SPITCH + 64 + h4];
        float4 gh = *(float4*)&spad[m * SPITCH + 128 + h4];
        float4 A4, B4;
        A4.x = sigf(gf.x); A4.y = sigf(gf.y);
        A4.z = sigf(gf.z); A4.w = sigf(gf.w);
        B4.x = sigf(gi.x) * gh.x; B4.y = sigf(gi.y) * gh.y;
        B4.z = sigf(gi.z) * gh.z; B4.w = sigf(gi.w) * gh.w;
        size_t base = (size_t)(m0 + m) * HDIM + h0 + h4;
        *(float4*)&g_A [base] = A4;
        *(float4*)&g_Bv[base] = B4;
        *(float4*)&As[m * APITCH + h4] = A4;
        *(float4*)&Bs[m * APITCH + h4] = B4;
    }
    __syncthreads();

    /* ---- fused chunk summary: 2 chunks x 64 h, 4-way fold + combine ---- */
    {
        const int q = tid >> 7, l = tid & 127;
        const int cl = l >> 6, hl = l & 63;
        const int bb = m0 >> 12;
        const int lr0 = cl * 64 + q * 16;
        const int* ip = is_init + bb * TLEN + (m0 & 4095) + lr0;
        float A = 1.f, Bv = 0.f, r = 0.f;
        #pragma unroll
        for (int s = 0; s < 16; ++s) {
            float a  = As[(lr0 + s) * APITCH + hl];
            float bv = Bs[(lr0 + s) * APITCH + hl];
            if (ip[s]) { A = a; Bv = bv; r = 1.f; }
            else       { Bv = fmaf(a, Bv, bv); A *= a; }
        }
        float* PA = (float*)(smem + G1_PA);
        float* PB = (float*)(smem + G1_PB);
        float* PR = (float*)(smem + G1_PR);
        PA[q * 128 + l] = A; PB[q * 128 + l] = Bv; PR[q * 128 + l] = r;
    }
    __syncthreads();
    if (tid < 128) {
        const int l = tid, cl = l >> 6, hl = l & 63;
        float* PA = (float*)(smem + G1_PA);
        float* PB = (float*)(smem + G1_PB);
        float* PR = (float*)(smem + G1_PR);
        float A = PA[l], Bv = PB[l], r = PR[l];
        #pragma unroll
        for (int q = 1; q < 4; ++q) {
            float A2 = PA[q * 128 + l], B2 = PB[q * 128 + l], r2 = PR[q * 128 + l];
            if (r2 > 0.f) { A = A2; Bv = B2; r = 1.f; }
            else          { Bv = fmaf(A2, Bv, B2); A *= A2; }
        }
        const int bb = m0 >> 12, c0 = (m0 & 4095) >> 6;
        int sidx = (bb * NC + c0 + cl) * HDIM + h0 + hl;
        g_sA[sidx] = A; g_sB[sidx] = Bv; g_sR[sidx] = r;
    }
}

/* =========================================================================
 * Output GEMM: out = (h_hi + h_lo) @ W_out_fp16.  512 thr, 128m x 128n,
 * K=512 in 16 chunks. Warps 4m x 4n, warp 32m x 32n. 4-stage pipeline.
 * ========================================================================= */
#define G2_AHI  0
#define G2_ALO  10240
#define G2_B    20480
#define G2_STG  30720
#define G2_SMEM (4 * G2_STG)     /* 122880 */

__global__ __launch_bounds__(512, 1) void out_mma_kernel(float* __restrict__ out)
{
    extern __shared__ char smem[];
    uint32_t sb = smem_u32(smem);
    const int tid = threadIdx.x, lane = tid & 31, wid = tid >> 5;
    const int m0 = blockIdx.x * 128, n0 = blockIdx.y * 128;
    const int wm = wid >> 2, wn = wid & 3;

    float acc[2][4][4];
    #pragma unroll
    for (int a = 0; a < 2; ++a)
        #pragma unroll
        for (int b = 0; b < 4; ++b)
            acc[a][b][0] = acc[a][b][1] = acc[a][b][2] = acc[a][b][3] = 0.f;

    const char* aH = (const char*)g_h_hi;
    const char* aL = (const char*)g_h_lo;
    const char* bG = (const char*)g_wo_h;

    /* 1536 segments, 3 per thread */
    #define G2_LOAD(c) do {                                                   \
        uint32_t stg = sb + ((c) & 3) * G2_STG;                               \
        int k0 = (c) * 32;                                                    \
        _Pragma("unroll")                                                     \
        for (int it = 0; it < 3; ++it) {                                      \
            int idx = tid + it * 512;                                         \
            if (idx < 1024) {                                                 \
                int sp = idx >> 9, rem = idx & 511, r = rem >> 2, sg = rem & 3; \
                const char* src = (sp ? aL : aH)                              \
                    + ((size_t)(m0 + r) * HDIM + k0) * 2 + sg * 16;           \
                CP_ASYNC16(stg + (sp ? G2_ALO : G2_AHI) + r * 80 + sg * 16, src); \
            } else {                                                          \
                int j = idx - 1024;                                           \
                int r = j >> 2, sg = j & 3;                                   \
                const char* src = bG                                          \
                    + ((size_t)(n0 + r) * HDIM + k0) * 2 + sg * 16;           \
                CP_ASYNC16(stg + G2_B + r * 80 + sg * 16, src);               \
            }                                                                 \
        }                                                                     \
        CP_COMMIT();                                                          \
    } while (0)

    G2_LOAD(0); G2_LOAD(1); G2_LOAD(2);
    #pragma unroll 1
    for (int c = 0; c < 16; ++c) {
        if (c <= 13)      { CP_WAIT(2); }
        else if (c == 14) { CP_WAIT(1); }
        else              { CP_WAIT(0); }
        __syncthreads();
        if (c + 3 < 16) G2_LOAD(c + 3);
        uint32_t stg = sb + (c & 3) * G2_STG;

        #pragma unroll
        for (int ks = 0; ks < 2; ++ks) {
            const int kb = ks * 32;
            uint32_t ah[2][4], al[2][4], bh[2][4];
            #pragma unroll
            for (int mi = 0; mi < 2; ++mi) {
                uint32_t ad = stg + G2_AHI
                    + (wm * 32 + mi * 16 + (lane & 15)) * 80
                    + (lane >> 4) * 16 + kb;
                ldsm4(ah[mi], ad);
                ldsm4(al[mi], ad + (G2_ALO - G2_AHI));
            }
            #pragma unroll
            for (int j = 0; j < 2; ++j) {
                int r = wn * 32 + j * 16 + ((lane >> 4) << 3) + (lane & 7);
                uint32_t bd = stg + G2_B + r * 80
                    + ((lane >> 3) & 1) * 16 + kb;
                ldsm4(bh[j], bd);
            }
            #pragma unroll
            for (int mi = 0; mi < 2; ++mi)
                #pragma unroll
                for (int nb = 0; nb < 4; ++nb) {
                    uint32_t b0 = bh[nb >> 1][(nb & 1) * 2];
                    uint32_t b1 = bh[nb >> 1][(nb & 1) * 2 + 1];
                    mma_f16(acc[mi][nb], ah[mi], b0, b1);
                    mma_f16(acc[mi][nb], al[mi], b0, b1);
                }
        }
    }

    /* direct epilogue */
    #pragma unroll
    for (int mi = 0; mi < 2; ++mi)
        #pragma unroll
        for (int nb = 0; nb < 4; ++nb) {
            int row = m0 + wm * 32 + mi * 16 + (lane >> 2);
            int col = n0 + wn * 32 + nb * 8 + (lane & 3) * 2;
            *(float2*)&out[(size_t)row * OUTF + col] =
                make_float2(acc[mi][nb][0], acc[mi][nb][1]);
            *(float2*)&out[(size_t)(row + 8) * OUTF + col] =
                make_float2(acc[mi][nb][2], acc[mi][nb][3]);
        }
}

/* ======================== scan kernels ================================== */
__global__ void chunk_scan_kernel(const float* __restrict__ h0p)
{
    int lane = blockIdx.x * blockDim.x + threadIdx.x;   /* < BSZ*H */
    int h = lane & (HDIM - 1);
    int b = lane >> 9;
    float h0v = h0p[b * HDIM + h];
    float hp = h0v;
    #pragma unroll 4
    for (int c = 0; c < NC; ++c) {
        int s = (b * NC + c) * HDIM + h;
        g_bound[s] = hp;
        float prev = (g_sR[s] > 0.f) ? h0v : hp;
        hp = fmaf(g_sA[s], prev, g_sB[s]);
    }
}

__global__ void apply_scan_kernel(const int* __restrict__ is_init,
                                  const float* __restrict__ h0p,
                                  float* __restrict__ hn_out)
{
    int lane = blockIdx.x * blockDim.x + threadIdx.x;
    int h  = lane & (HDIM - 1);
    int bc = lane >> 9;
    int c  = bc & (NC - 1);
    int b  = bc >> 6;
    int t0 = c * CHUNK;

    float h0v = h0p[b * HDIM + h];
    float hv  = g_bound[lane];
    size_t idx = ((size_t)(b * TLEN + t0)) * HDIM + h;
    const int* ip = is_init + b * TLEN + t0;

    #pragma unroll 4
    for (int t = 0; t < CHUNK; ++t, idx += HDIM) {
        float a  = g_A[idx];
        float bv = g_Bv[idx];
        float prev = ip[t] ? h0v : hv;
        hv = fmaf(a, prev, bv);
        __half hh = __float2half_rn(hv);
        g_h_hi[idx] = __half_as_ushort(hh);
        g_h_lo[idx] = __half_as_ushort(
            __float2half_rn(hv - __half2float(hh)));
    }
    if (c == NC - 1) hn_out[b * HDIM + h] = hv;
}

/* ========================================================================= */
extern "C" void kernel_launch(void* const* d_in, const int* in_sizes, int n_in,
                              void* d_out, int out_size)
{
    const float* inp  = (const float*)d_in[0];   /* (8,4096,256)  */
    const int*   isin = (const int*)  d_in[1];   /* (8,4096,1)    */
    const float* h0   = (const float*)d_in[2];   /* (8,1,512)     */
    const float* Whg  = (const float*)d_in[3];   /* (256,1536)    */
    const float* Wout = (const float*)d_in[4];   /* (512,256)     */
    float* out = (float*)d_out;                  /* out then h_n  */

    cudaFuncSetAttribute(gates_mma_kernel,
                         cudaFuncAttributeMaxDynamicSharedMemorySize, G1_SMEM);
    cudaFuncSetAttribute(out_mma_kernel,
                         cudaFuncAttributeMaxDynamicSharedMemorySize, G2_SMEM);

    conv_input_kernel<<<(MROWS * INF / 4) / 256, 256>>>(inp);
    conv_whg_kernel<<<(3 * HDIM * INF) / 256, 256>>>(Whg);
    conv_wout_kernel<<<(OUTF * HDIM) / 256, 256>>>(Wout);

    gates_mma_kernel<<<dim3(MROWS / 128, HDIM / 64), 512, G1_SMEM>>>(isin);

    chunk_scan_kernel<<<(BSZ * HDIM) / 256, 256>>>(h0);
    apply_scan_kernel<<<(BSZ * NC * HDIM) / 256, 256>>>(isin, h0,
                                                        out + (size_t)MROWS * OUTF);

    out_mma_kernel<<<dim3(MROWS / 128, OUTF / 128), 512, G2_SMEM>>>(out);
}

// round 11
// speedup vs baseline: 2.4064x; 1.0754x over previous
#include <cuda_runtime.h>
#include <cuda_fp16.h>
#include <cstdint>
#include <math.h>

#define BSZ   8
#define TLEN  4096
#define INF   256
#define HDIM  512
#define OUTF  256
#define MROWS (BSZ*TLEN)     /* 32768 */
#define CHUNK 64
#define NC    (TLEN/CHUNK)   /* 64 */

/* ---------------- scratch (device globals; no runtime allocation) -------- */
__device__ __align__(16) float g_A [(size_t)MROWS*HDIM];
__device__ __align__(16) float g_Bv[(size_t)MROWS*HDIM];
__device__ __align__(16) unsigned short g_in_h[(size_t)MROWS*INF];     /* fp16 */
__device__ __align__(16) unsigned short g_Wg_hi[3*HDIM*INF];  /* [1536][256] */
__device__ __align__(16) unsigned short g_Wg_lo[3*HDIM*INF];
__device__ __align__(16) unsigned short g_wo_h[OUTF*HDIM];    /* [256][512]  */
__device__ __align__(16) unsigned short g_h_hi[(size_t)MROWS*HDIM];
__device__ __align__(16) float g_sA[BSZ*NC*HDIM];
__device__ __align__(16) float g_sB[BSZ*NC*HDIM];
__device__ __align__(16) float g_sR[BSZ*NC*HDIM];
__device__ __align__(16) float g_bound[BSZ*NC*HDIM];

__device__ __forceinline__ float sigf(float x) {
    return 1.0f / (1.0f + __expf(-x));
}

__device__ __forceinline__ uint32_t smem_u32(const void* p) {
    uint32_t a;
    asm("{ .reg .u64 t; cvta.to.shared.u64 t, %1; cvt.u32.u64 %0, t; }"
        : "=r"(a) : "l"(p));
    return a;
}

#define CP_ASYNC16(dst, src) \
    asm volatile("cp.async.cg.shared.global [%0], [%1], 16;" :: "r"(dst), "l"(src))
#define CP_COMMIT()  asm volatile("cp.async.commit_group;" ::: "memory")
#define CP_WAIT(N)   asm volatile("cp.async.wait_group %0;" :: "n"(N) : "memory")

__device__ __forceinline__ void ldsm4(uint32_t r[4], uint32_t addr) {
    asm volatile("ldmatrix.sync.aligned.m8n8.x4.shared.b16 {%0,%1,%2,%3}, [%4];"
        : "=r"(r[0]), "=r"(r[1]), "=r"(r[2]), "=r"(r[3]) : "r"(addr));
}

__device__ __forceinline__ void mma_f16(float c[4], const uint32_t a[4],
                                        uint32_t b0, uint32_t b1) {
    asm volatile(
        "mma.sync.aligned.m16n8k16.row.col.f32.f16.f16.f32 "
        "{%0,%1,%2,%3}, {%4,%5,%6,%7}, {%8,%9}, {%0,%1,%2,%3};"
        : "+f"(c[0]), "+f"(c[1]), "+f"(c[2]), "+f"(c[3])
        : "r"(a[0]), "r"(a[1]), "r"(a[2]), "r"(a[3]), "r"(b0), "r"(b1));
}

/* ====================== conversion / split kernels ======================= */
__global__ void conv_input_kernel(const float* __restrict__ x)
{
    int i = blockIdx.x * blockDim.x + threadIdx.x;       /* per float4 */
    float4 v = ((const float4*)x)[i];
    ushort4 hv;
    hv.x = __half_as_ushort(__float2half_rn(v.x));
    hv.y = __half_as_ushort(__float2half_rn(v.y));
    hv.z = __half_as_ushort(__float2half_rn(v.z));
    hv.w = __half_as_ushort(__float2half_rn(v.w));
    ((ushort4*)g_in_h)[i] = hv;
}

__global__ void conv_whg_kernel(const float* __restrict__ W)
{
    int i = blockIdx.x * blockDim.x + threadIdx.x;  /* i = n*256 + k */
    int n = i >> 8, k = i & 255;
    float v = W[(size_t)k * (3 * HDIM) + n];
    __half h = __float2half_rn(v);
    g_Wg_hi[i] = __half_as_ushort(h);
    g_Wg_lo[i] = __half_as_ushort(__float2half_rn(v - __half2float(h)));
}

__global__ void conv_wout_kernel(const float* __restrict__ W)
{
    int i = blockIdx.x * blockDim.x + threadIdx.x;  /* i = n*512 + k */
    int n = i >> 9, k = i & 511;
    g_wo_h[i] = __half_as_ushort(__float2half_rn(W[(size_t)k * OUTF + n]));
}

/* =========================================================================
 * Gates GEMM (fp16 2-pass: in_fp16 x (W_hi + W_lo)) + fused sigmoid
 * epilogue + fused per-chunk scan summary.
 * CTA: 512 thr, 128 m x (3 gates x 64 h). Warps 4m x 4n, warp 32m x 48n.
 * K=256 in 8 chunks of 32, cp.async 4-stage pipeline.
 * Inner loop interleaves ldsm->mma per B-fragment for SB-friendly overlap.
 * ========================================================================= */
#define G1_A    0
#define G1_BHI  10240
#define G1_BLO  25600
#define G1_STG  40960
#define G1_AS   100352
#define G1_BS   135168
#define G1_PA   169984
#define G1_PB   172032
#define G1_PR   174080
#define G1_SMEM 176128
#define SPITCH  196
#define APITCH  68

__global__ __launch_bounds__(512, 1)
void gates_mma_kernel(const int* __restrict__ is_init)
{
    extern __shared__ char smem[];
    uint32_t sb = smem_u32(smem);
    const int tid = threadIdx.x, lane = tid & 31, wid = tid >> 5;
    const int m0 = blockIdx.x * 128, h0 = blockIdx.y * 64;
    const int wm = wid >> 2, wn = wid & 3;

    float acc[2][6][4];
    #pragma unroll
    for (int a = 0; a < 2; ++a)
        #pragma unroll
        for (int b = 0; b < 6; ++b)
            acc[a][b][0] = acc[a][b][1] = acc[a][b][2] = acc[a][b][3] = 0.f;

    const char* aG = (const char*)g_in_h;
    const char* bH = (const char*)g_Wg_hi;
    const char* bL = (const char*)g_Wg_lo;

    /* ---- chunk loader: 2048 x 16B segments, 4 per thread ---- */
    #define G1_LOAD(c) do {                                                   \
        uint32_t stg = sb + ((c) & 3) * G1_STG;                               \
        int k0 = (c) * 32;                                                    \
        _Pragma("unroll")                                                     \
        for (int it = 0; it < 4; ++it) {                                      \
            int idx = tid + it * 512;                                         \
            if (idx < 512) {                                                  \
                int r = idx >> 2, sg = idx & 3;                               \
                const char* src = aG                                          \
                    + ((size_t)(m0 + r) * INF + k0) * 2 + sg * 16;            \
                CP_ASYNC16(stg + G1_A + r * 80 + sg * 16, src);               \
            } else {                                                          \
                int j = idx - 512;                                            \
                int sp = (j >= 768) ? 1 : 0, rem = j - sp * 768;              \
                int r = rem >> 2, sg = rem & 3;                               \
                const char* src = (sp ? bL : bH)                              \
                    + ((size_t)((r >> 6) * HDIM + h0 + (r & 63)) * INF + k0) * 2 \
                    + sg * 16;                                                \
                CP_ASYNC16(stg + (sp ? G1_BLO : G1_BHI) + r * 80 + sg * 16, src); \
            }                                                                 \
        }                                                                     \
        CP_COMMIT();                                                          \
    } while (0)

    G1_LOAD(0); G1_LOAD(1); G1_LOAD(2);
    #pragma unroll 1
    for (int c = 0; c < 8; ++c) {
        if (c <= 5)      { CP_WAIT(2); }
        else if (c == 6) { CP_WAIT(1); }
        else             { CP_WAIT(0); }
        __syncthreads();
        if (c + 3 < 8) G1_LOAD(c + 3);
        uint32_t stg = sb + (c & 3) * G1_STG;

        #pragma unroll
        for (int ks = 0; ks < 2; ++ks) {
            const int kb = ks * 32;                 /* 16 elems = 32 bytes */
            uint32_t ah[2][4];
            #pragma unroll
            for (int mi = 0; mi < 2; ++mi) {
                uint32_t ad = stg + G1_A
                    + (wm * 32 + mi * 16 + (lane & 15)) * 80
                    + (lane >> 4) * 16 + kb;
                ldsm4(ah[mi], ad);
            }
            /* interleaved: ldsm fragment j, then its 8 mmas while j+1 flies */
            #pragma unroll
            for (int j = 0; j < 3; ++j) {
                uint32_t bh[4], bl[4];
                int r = wn * 48 + j * 16 + ((lane >> 4) << 3) + (lane & 7);
                uint32_t bd = stg + G1_BHI + r * 80
                    + ((lane >> 3) & 1) * 16 + kb;
                ldsm4(bh, bd);
                ldsm4(bl, bd + (G1_BLO - G1_BHI));
                #pragma unroll
                for (int mi = 0; mi < 2; ++mi)
                    #pragma unroll
                    for (int s = 0; s < 2; ++s) {
                        int nb = j * 2 + s;
                        mma_f16(acc[mi][nb], ah[mi], bh[s*2], bh[s*2+1]);
                        mma_f16(acc[mi][nb], ah[mi], bl[s*2], bl[s*2+1]);
                    }
            }
        }
    }
    __syncthreads();

    /* ---- epilogue: stage accums, fuse sigmoid ---- */
    float* spad = (float*)smem;
    #pragma unroll
    for (int mi = 0; mi < 2; ++mi)
        #pragma unroll
        for (int nb = 0; nb < 6; ++nb) {
            int row = wm * 32 + mi * 16 + (lane >> 2);
            int col = wn * 48 + nb * 8 + (lane & 3) * 2;
            spad[row * SPITCH + col]           = acc[mi][nb][0];
            spad[row * SPITCH + col + 1]       = acc[mi][nb][1];
            spad[(row + 8) * SPITCH + col]     = acc[mi][nb][2];
            spad[(row + 8) * SPITCH + col + 1] = acc[mi][nb][3];
        }
    __syncthreads();

    float* As = (float*)(smem + G1_AS);
    float* Bs = (float*)(smem + G1_BS);
    const int h4 = (tid & 15) * 4, mr = tid >> 4;    /* mr: 0..31 */
    #pragma unroll
    for (int i = 0; i < 4; ++i) {
        int m = mr + i * 32;
        float4 gf = *(float4*)&spad[m * SPITCH + h4];
        float4 gi = *(float4*)&spad[m * SPITCH + 64 + h4];
        float4 gh = *(float4*)&spad[m * SPITCH + 128 + h4];
        float4 A4, B4;
        A4.x = sigf(gf.x); A4.y = sigf(gf.y);
        A4.z = sigf(gf.z); A4.w = sigf(gf.w);
        B4.x = sigf(gi.x) * gh.x; B4.y = sigf(gi.y) * gh.y;
        B4.z = sigf(gi.z) * gh.z; B4.w = sigf(gi.w) * gh.w;
        size_t base = (size_t)(m0 + m) * HDIM + h0 + h4;
        *(float4*)&g_A [base] = A4;
        *(float4*)&g_Bv[base] = B4;
        *(float4*)&As[m * APITCH + h4] = A4;
        *(float4*)&Bs[m * APITCH + h4] = B4;
    }
    __syncthreads();

    /* ---- fused chunk summary: 2 chunks x 64 h, 4-way fold + combine ---- */
    {
        const int q = tid >> 7, l = tid & 127;
        const int cl = l >> 6, hl = l & 63;
        const int bb = m0 >> 12;
        const int lr0 = cl * 64 + q * 16;
        const int* ip = is_init + bb * TLEN + (m0 & 4095) + lr0;
        float A = 1.f, Bv = 0.f, r = 0.f;
        #pragma unroll
        for (int s = 0; s < 16; ++s) {
            float a  = As[(lr0 + s) * APITCH + hl];
            float bv = Bs[(lr0 + s) * APITCH + hl];
            if (ip[s]) { A = a; Bv = bv; r = 1.f; }
            else       { Bv = fmaf(a, Bv, bv); A *= a; }
        }
        float* PA = (float*)(smem + G1_PA);
        float* PB = (float*)(smem + G1_PB);
        float* PR = (float*)(smem + G1_PR);
        PA[q * 128 + l] = A; PB[q * 128 + l] = Bv; PR[q * 128 + l] = r;
    }
    __syncthreads();
    if (tid < 128) {
        const int l = tid, cl = l >> 6, hl = l & 63;
        float* PA = (float*)(smem + G1_PA);
        float* PB = (float*)(smem + G1_PB);
        float* PR = (float*)(smem + G1_PR);
        float A = PA[l], Bv = PB[l], r = PR[l];
        #pragma unroll
        for (int q = 1; q < 4; ++q) {
            float A2 = PA[q * 128 + l], B2 = PB[q * 128 + l], r2 = PR[q * 128 + l];
            if (r2 > 0.f) { A = A2; Bv = B2; r = 1.f; }
            else          { Bv = fmaf(A2, Bv, B2); A *= A2; }
        }
        const int bb = m0 >> 12, c0 = (m0 & 4095) >> 6;
        int sidx = (bb * NC + c0 + cl) * HDIM + h0 + hl;
        g_sA[sidx] = A; g_sB[sidx] = Bv; g_sR[sidx] = r;
    }
}

/* =========================================================================
 * Output GEMM: out = h_fp16 @ W_out_fp16 (single pass).  512 thr,
 * 128m x 128n, K=512 in 16 chunks. Warps 4m x 4n, warp 32m x 32n.
 * 4-stage pipeline, interleaved ldsm/mma.
 * ========================================================================= */
#define G2_A    0
#define G2_B    10240
#define G2_STG  20480
#define G2_SMEM (4 * G2_STG)     /* 81920 */

__global__ __launch_bounds__(512, 1) void out_mma_kernel(float* __restrict__ out)
{
    extern __shared__ char smem[];
    uint32_t sb = smem_u32(smem);
    const int tid = threadIdx.x, lane = tid & 31, wid = tid >> 5;
    const int m0 = blockIdx.x * 128, n0 = blockIdx.y * 128;
    const int wm = wid >> 2, wn = wid & 3;

    float acc[2][4][4];
    #pragma unroll
    for (int a = 0; a < 2; ++a)
        #pragma unroll
        for (int b = 0; b < 4; ++b)
            acc[a][b][0] = acc[a][b][1] = acc[a][b][2] = acc[a][b][3] = 0.f;

    const char* aG = (const char*)g_h_hi;
    const char* bG = (const char*)g_wo_h;

    /* 1024 segments, 2 per thread */
    #define G2_LOAD(c) do {                                                   \
        uint32_t stg = sb + ((c) & 3) * G2_STG;                               \
        int k0 = (c) * 32;                                                    \
        _Pragma("unroll")                                                     \
        for (int it = 0; it < 2; ++it) {                                      \
            int idx = tid + it * 512;                                         \
            if (idx < 512) {                                                  \
                int r = idx >> 2, sg = idx & 3;                               \
                const char* src = aG                                          \
                    + ((size_t)(m0 + r) * HDIM + k0) * 2 + sg * 16;           \
                CP_ASYNC16(stg + G2_A + r * 80 + sg * 16, src);               \
            } else {                                                          \
                int j = idx - 512;                                            \
                int r = j >> 2, sg = j & 3;                                   \
                const char* src = bG                                          \
                    + ((size_t)(n0 + r) * HDIM + k0) * 2 + sg * 16;           \
                CP_ASYNC16(stg + G2_B + r * 80 + sg * 16, src);               \
            }                                                                 \
        }                                                                     \
        CP_COMMIT();                                                          \
    } while (0)

    G2_LOAD(0); G2_LOAD(1); G2_LOAD(2);
    #pragma unroll 1
    for (int c = 0; c < 16; ++c) {
        if (c <= 13)      { CP_WAIT(2); }
        else if (c == 14) { CP_WAIT(1); }
        else              { CP_WAIT(0); }
        __syncthreads();
        if (c + 3 < 16) G2_LOAD(c + 3);
        uint32_t stg = sb + (c & 3) * G2_STG;

        #pragma unroll
        for (int ks = 0; ks < 2; ++ks) {
            const int kb = ks * 32;
            uint32_t ah[2][4];
            #pragma unroll
            for (int mi = 0; mi < 2; ++mi) {
                uint32_t ad = stg + G2_A
                    + (wm * 32 + mi * 16 + (lane & 15)) * 80
                    + (lane >> 4) * 16 + kb;
                ldsm4(ah[mi], ad);
            }
            #pragma unroll
            for (int j = 0; j < 2; ++j) {
                uint32_t bh[4];
                int r = wn * 32 + j * 16 + ((lane >> 4) << 3) + (lane & 7);
                uint32_t bd = stg + G2_B + r * 80
                    + ((lane >> 3) & 1) * 16 + kb;
                ldsm4(bh, bd);
                #pragma unroll
                for (int mi = 0; mi < 2; ++mi)
                    #pragma unroll
                    for (int s = 0; s < 2; ++s) {
                        int nb = j * 2 + s;
                        mma_f16(acc[mi][nb], ah[mi], bh[s*2], bh[s*2+1]);
                    }
            }
        }
    }

    /* direct epilogue */
    #pragma unroll
    for (int mi = 0; mi < 2; ++mi)
        #pragma unroll
        for (int nb = 0; nb < 4; ++nb) {
            int row = m0 + wm * 32 + mi * 16 + (lane >> 2);
            int col = n0 + wn * 32 + nb * 8 + (lane & 3) * 2;
            *(float2*)&out[(size_t)row * OUTF + col] =
                make_float2(acc[mi][nb][0], acc[mi][nb][1]);
            *(float2*)&out[(size_t)(row + 8) * OUTF + col] =
                make_float2(acc[mi][nb][2], acc[mi][nb][3]);
        }
}

/* ======================== scan kernels ================================== */
__global__ void chunk_scan_kernel(const float* __restrict__ h0p)
{
    int lane = blockIdx.x * blockDim.x + threadIdx.x;   /* < BSZ*H */
    int h = lane & (HDIM - 1);
    int b = lane >> 9;
    float h0v = h0p[b * HDIM + h];
    float hp = h0v;
    #pragma unroll 4
    for (int c = 0; c < NC; ++c) {
        int s = (b * NC + c) * HDIM + h;
        g_bound[s] = hp;
        float prev = (g_sR[s] > 0.f) ? h0v : hp;
        hp = fmaf(g_sA[s], prev, g_sB[s]);
    }
}

__global__ void apply_scan_kernel(const int* __restrict__ is_init,
                                  const float* __restrict__ h0p,
                                  float* __restrict__ hn_out)
{
    int lane = blockIdx.x * blockDim.x + threadIdx.x;
    int h  = lane & (HDIM - 1);
    int bc = lane >> 9;
    int c  = bc & (NC - 1);
    int b  = bc >> 6;
    int t0 = c * CHUNK;

    float h0v = h0p[b * HDIM + h];
    float hv  = g_bound[lane];
    size_t idx = ((size_t)(b * TLEN + t0)) * HDIM + h;
    const int* ip = is_init + b * TLEN + t0;

    #pragma unroll 4
    for (int t = 0; t < CHUNK; ++t, idx += HDIM) {
        float a  = g_A[idx];
        float bv = g_Bv[idx];
        float prev = ip[t] ? h0v : hv;
        hv = fmaf(a, prev, bv);
        g_h_hi[idx] = __half_as_ushort(__float2half_rn(hv));
    }
    if (c == NC - 1) hn_out[b * HDIM + h] = hv;
}

/* ========================================================================= */
extern "C" void kernel_launch(void* const* d_in, const int* in_sizes, int n_in,
                              void* d_out, int out_size)
{
    const float* inp  = (const float*)d_in[0];   /* (8,4096,256)  */
    const int*   isin = (const int*)  d_in[1];   /* (8,4096,1)    */
    const float* h0   = (const float*)d_in[2];   /* (8,1,512)     */
    const float* Whg  = (const float*)d_in[3];   /* (256,1536)    */
    const float* Wout = (const float*)d_in[4];   /* (512,256)     */
    float* out = (float*)d_out;                  /* out then h_n  */

    cudaFuncSetAttribute(gates_mma_kernel,
                         cudaFuncAttributeMaxDynamicSharedMemorySize, G1_SMEM);
    cudaFuncSetAttribute(out_mma_kernel,
                         cudaFuncAttributeMaxDynamicSharedMemorySize, G2_SMEM);

    conv_input_kernel<<<(MROWS * INF / 4) / 256, 256>>>(inp);
    conv_whg_kernel<<<(3 * HDIM * INF) / 256, 256>>>(Whg);
    conv_wout_kernel<<<(OUTF * HDIM) / 256, 256>>>(Wout);

    gates_mma_kernel<<<dim3(MROWS / 128, HDIM / 64), 512, G1_SMEM>>>(isin);

    chunk_scan_kernel<<<(BSZ * HDIM) / 256, 256>>>(h0);
    apply_scan_kernel<<<(BSZ * NC * HDIM) / 256, 256>>>(isin, h0,
                                                        out + (size_t)MROWS * OUTF);

    out_mma_kernel<<<dim3(MROWS / 128, OUTF / 128), 512, G2_SMEM>>>(out);
}